// round 7
// baseline (speedup 1.0000x reference)
#include <cuda_runtime.h>

// loss = sum_{rows, j>=1} relu(|x[:,j]-x[:,j-1]|-1) * mask[:,j]
// x, mask: [65536, 512] fp32. 256 MB HBM streaming reduction, LTS-cap bound.
// R2 structure (best measured), retuned: 512x512 single wave, unroll 8.

#define THREADS   512
#define BLOCKS    512           // one wave; 512*512 threads
#define ITERS     32            // 8388608 float4s / (512*512) == 32 exactly
#define ROW_F4    128           // float4s per 512-float row

__device__ float        g_partials[BLOCKS];
__device__ unsigned int g_ticket = 0;   // zero-init; reset by last block each run

__global__ __launch_bounds__(THREADS)
void connect_loss_kernel(const float* __restrict__ x,
                         const float* __restrict__ mask,
                         float* __restrict__ out) {
    const float4* __restrict__ x4 = reinterpret_cast<const float4*>(x);
    const float4* __restrict__ m4 = reinterpret_cast<const float4*>(mask);

    const long long stride = (long long)BLOCKS * THREADS;   // multiple of ROW_F4
    long long i = (long long)blockIdx.x * THREADS + threadIdx.x;
    const int lane = threadIdx.x & 31;
    // position-in-row is loop-invariant: stride % 128 == 0
    const int c = (int)(i & (ROW_F4 - 1));
    const bool fixup = (lane == 0) && (c != 0);   // lane 0 mid-row: cross-warp neighbor
    const bool rowstart = (c == 0);               // column 0 contributes 0

    float s = 0.0f;

    #pragma unroll 8
    for (int it = 0; it < ITERS; ++it, i += stride) {
        float4 v = x4[i];
        float4 m = m4[i];

        // previous element lives in lane-1's v.w (contiguous float4 -> contiguous lane)
        float prev = __shfl_up_sync(0xffffffffu, v.w, 1);
        if (fixup) prev = x[4 * i - 1];

        float d0 = fmaxf(fabsf(v.x - prev) - 1.0f, 0.0f) * m.x;
        float acc = rowstart ? 0.0f : d0;
        acc += fmaxf(fabsf(v.y - v.x) - 1.0f, 0.0f) * m.y;
        acc += fmaxf(fabsf(v.z - v.y) - 1.0f, 0.0f) * m.z;
        acc += fmaxf(fabsf(v.w - v.z) - 1.0f, 0.0f) * m.w;
        s += acc;
    }

    // ---- block reduction ----
    __shared__ float red[THREADS / 32];
    __shared__ bool  amLast;
    const int w = threadIdx.x >> 5;

    #pragma unroll
    for (int o = 16; o > 0; o >>= 1)
        s += __shfl_xor_sync(0xffffffffu, s, o);

    if (lane == 0) red[w] = s;
    __syncthreads();

    if (threadIdx.x == 0) {
        float bs = 0.0f;
        #pragma unroll
        for (int k = 0; k < THREADS / 32; ++k) bs += red[k];
        g_partials[blockIdx.x] = bs;
        __threadfence();
        unsigned int t = atomicAdd(&g_ticket, 1u);
        amLast = (t == BLOCKS - 1);
    }
    __syncthreads();

    // ---- last block: deterministic final reduction over 512 partials ----
    if (amLast) {
        __threadfence();
        float v = g_partials[threadIdx.x];        // BLOCKS == THREADS

        #pragma unroll
        for (int o = 16; o > 0; o >>= 1)
            v += __shfl_xor_sync(0xffffffffu, v, o);

        if (lane == 0) red[w] = v;
        __syncthreads();

        if (threadIdx.x == 0) {
            float total = 0.0f;
            #pragma unroll
            for (int k = 0; k < THREADS / 32; ++k) total += red[k];
            out[0] = total;
            g_ticket = 0;   // reset for next graph replay
        }
    }
}

extern "C" void kernel_launch(void* const* d_in, const int* in_sizes, int n_in,
                              void* d_out, int out_size) {
    const float* x    = (const float*)d_in[0];
    const float* mask = (const float*)d_in[1];
    float* out = (float*)d_out;

    connect_loss_kernel<<<BLOCKS, THREADS>>>(x, mask, out);
}

// round 8
// speedup vs baseline: 1.2386x; 1.2386x over previous
#include <cuda_runtime.h>

// loss = sum_{rows, j>=1} relu(|x[:,j]-x[:,j-1]|-1) * mask[:,j]
// x, mask: [65536, 512] fp32. 256 MB HBM streaming reduction (~6 TB/s ceiling).
// R2 structure with perfectly balanced grid: 1184 = 8*148 blocks -> exactly
// 8 resident 256-thread blocks per SM, no static load imbalance.

#define THREADS   256
#define BLOCKS    1184          // 8 blocks/SM * 148 SMs, single full wave
#define ROW_F4    128           // float4s per 512-float row
#define N4        8388608LL     // total float4s per array

__device__ float        g_partials[BLOCKS];
__device__ unsigned int g_ticket = 0;   // zero-init; reset by last block each run

__global__ __launch_bounds__(THREADS)
void connect_loss_kernel(const float* __restrict__ x,
                         const float* __restrict__ mask,
                         float* __restrict__ out) {
    const float4* __restrict__ x4 = reinterpret_cast<const float4*>(x);
    const float4* __restrict__ m4 = reinterpret_cast<const float4*>(mask);

    const long long stride = (long long)BLOCKS * THREADS;   // 303104, multiple of 128
    long long i = (long long)blockIdx.x * THREADS + threadIdx.x;
    const int lane = threadIdx.x & 31;
    // position-in-row is loop-invariant: stride % 128 == 0
    const int c = (int)(i & (ROW_F4 - 1));
    const bool fixup = (lane == 0) && (c != 0);   // lane 0 mid-row: cross-warp neighbor
    const bool rowstart = (c == 0);               // column 0 contributes 0

    float s = 0.0f;

    #pragma unroll 4
    for (; i < N4; i += stride) {
        float4 v = x4[i];
        float4 m = m4[i];

        // previous element lives in lane-1's v.w (contiguous float4 -> contiguous lane)
        float prev = __shfl_up_sync(0xffffffffu, v.w, 1);
        if (fixup) prev = x[4 * i - 1];

        float d0 = fmaxf(fabsf(v.x - prev) - 1.0f, 0.0f) * m.x;
        float acc = rowstart ? 0.0f : d0;
        acc += fmaxf(fabsf(v.y - v.x) - 1.0f, 0.0f) * m.y;
        acc += fmaxf(fabsf(v.z - v.y) - 1.0f, 0.0f) * m.z;
        acc += fmaxf(fabsf(v.w - v.z) - 1.0f, 0.0f) * m.w;
        s += acc;
    }

    // ---- block reduction ----
    __shared__ float red[THREADS / 32];
    __shared__ bool  amLast;
    const int w = threadIdx.x >> 5;

    #pragma unroll
    for (int o = 16; o > 0; o >>= 1)
        s += __shfl_xor_sync(0xffffffffu, s, o);

    if (lane == 0) red[w] = s;
    __syncthreads();

    if (threadIdx.x == 0) {
        float bs = 0.0f;
        #pragma unroll
        for (int k = 0; k < THREADS / 32; ++k) bs += red[k];
        g_partials[blockIdx.x] = bs;
        __threadfence();
        unsigned int t = atomicAdd(&g_ticket, 1u);
        amLast = (t == BLOCKS - 1);
    }
    __syncthreads();

    // ---- last block: deterministic final reduction over 1184 partials ----
    if (amLast) {
        __threadfence();
        float v = 0.0f;
        #pragma unroll
        for (int k = 0; k < 5; ++k) {                 // ceil(1184/256) = 5
            int idx = threadIdx.x + k * THREADS;
            if (idx < BLOCKS) v += g_partials[idx];
        }

        #pragma unroll
        for (int o = 16; o > 0; o >>= 1)
            v += __shfl_xor_sync(0xffffffffu, v, o);

        if (lane == 0) red[w] = v;
        __syncthreads();

        if (threadIdx.x == 0) {
            float total = 0.0f;
            #pragma unroll
            for (int k = 0; k < THREADS / 32; ++k) total += red[k];
            out[0] = total;
            g_ticket = 0;   // reset for next graph replay
        }
    }
}

extern "C" void kernel_launch(void* const* d_in, const int* in_sizes, int n_in,
                              void* d_out, int out_size) {
    const float* x    = (const float*)d_in[0];
    const float* mask = (const float*)d_in[1];
    float* out = (float*)d_out;

    connect_loss_kernel<<<BLOCKS, THREADS>>>(x, mask, out);
}